// round 1
// baseline (speedup 1.0000x reference)
#include <cuda_runtime.h>

#define HW (512 * 512)
#define HW4 (HW / 4)

__device__ __forceinline__ void adjust_px(float r, float g, float b,
                                          float dh, float ds,
                                          float& ro, float& go, float& bo) {
    // --- rgb2hsv (matching reference semantics) ---
    float maxc = fmaxf(r, fmaxf(g, b));
    float minc = fminf(r, fminf(g, b));
    bool  eqc  = (maxc == minc);
    float cr   = maxc - minc;
    float s    = cr / (eqc ? 1.0f : maxc);
    float crd  = eqc ? 1.0f : cr;
    float inv  = 1.0f / crd;
    float rc = (maxc - r) * inv;
    float gc = (maxc - g) * inv;
    float bc = (maxc - b) * inv;

    float hsum;
    if (maxc == r)       hsum = bc - gc;                 // hr branch
    else if (maxc == g)  hsum = 2.0f + rc - bc;          // hg branch (maxc!=r)
    else                 hsum = 4.0f + gc - rc;          // hb branch

    float h = hsum * (1.0f / 6.0f);
    h = h - floorf(h);           // == mod(hsum, 6) / 6

    // --- apply transform ---
    h = h + dh;
    h = h - floorf(h);           // mod(h + dh, 1)
    s = __saturatef(s * ds);     // clip(s * ds, 0, 1)
    float v = maxc;

    // --- hsv2rgb ---
    float h6  = h * 6.0f;
    float i_f = floorf(h6);
    float f   = h6 - i_f;
    int   i   = ((int)i_f) % 6;
    float p = __saturatef(v * (1.0f - s));
    float q = __saturatef(v * (1.0f - s * f));
    float t = __saturatef(v * (1.0f - s * (1.0f - f)));

    switch (i) {
        case 0: ro = v; go = t; bo = p; break;
        case 1: ro = q; go = v; bo = p; break;
        case 2: ro = p; go = v; bo = t; break;
        case 3: ro = p; go = q; bo = v; break;
        case 4: ro = t; go = p; bo = v; break;
        default: ro = v; go = p; bo = q; break;
    }
}

__global__ __launch_bounds__(256)
void adjust_hue_sat_kernel(const float* __restrict__ imgs,
                           const float* __restrict__ xform,
                           float* __restrict__ out) {
    int batch = blockIdx.y;
    int idx   = blockIdx.x * blockDim.x + threadIdx.x;   // float4 index within plane
    if (idx >= HW4) return;

    float dh = __ldg(&xform[2 * batch]);
    float ds = __ldg(&xform[2 * batch + 1]);

    const float4* Rin = (const float4*)(imgs + (size_t)batch * 3 * HW);
    const float4* Gin = Rin + HW4;
    const float4* Bin = Gin + HW4;

    float4 r4 = Rin[idx];
    float4 g4 = Gin[idx];
    float4 b4 = Bin[idx];

    float4 ro4, go4, bo4;
    adjust_px(r4.x, g4.x, b4.x, dh, ds, ro4.x, go4.x, bo4.x);
    adjust_px(r4.y, g4.y, b4.y, dh, ds, ro4.y, go4.y, bo4.y);
    adjust_px(r4.z, g4.z, b4.z, dh, ds, ro4.z, go4.z, bo4.z);
    adjust_px(r4.w, g4.w, b4.w, dh, ds, ro4.w, go4.w, bo4.w);

    float4* Rout = (float4*)(out + (size_t)batch * 3 * HW);
    float4* Gout = Rout + HW4;
    float4* Bout = Gout + HW4;
    Rout[idx] = ro4;
    Gout[idx] = go4;
    Bout[idx] = bo4;
}

extern "C" void kernel_launch(void* const* d_in, const int* in_sizes, int n_in,
                              void* d_out, int out_size) {
    const float* imgs  = (const float*)d_in[0];
    const float* xform = (const float*)d_in[1];
    float*       out   = (float*)d_out;

    dim3 block(256);
    dim3 grid(HW4 / 256, 64);   // 256 blocks/plane-quarter, 64 batches
    adjust_hue_sat_kernel<<<grid, block>>>(imgs, xform, out);
}